// round 14
// baseline (speedup 1.0000x reference)
#include <cuda_runtime.h>
#include <cuda_fp16.h>
#include <math.h>

#define TWO_PI 6.283185307179586f

// ---- static device scratch (allocation-free) ----
// Single reused FFT intermediate (33.5 MB -> stays L2-resident between p1/p2)
__device__ __align__(16) __half2 g_A [256 * 256 * 128];
// Sampled volumes, channel-last fp16: V[u][v][c]
__device__ __align__(16) __half2 g_Vx[256 * 256 * 128];
__device__ __align__(16) __half2 g_Vy[256 * 256 * 128];
__device__ __align__(16) __half2 g_Vz[256 * 256 * 128];

#define SH_R 273   // smem row stride (float2 units)

// ---------------------------------------------------------------------------
// complex helpers
// ---------------------------------------------------------------------------
__device__ __forceinline__ float2 cmul(float2 a, float2 b) {
    return make_float2(fmaf(a.x, b.x, -a.y * b.y), fmaf(a.x, b.y, a.y * b.x));
}
__device__ __forceinline__ float2 cmul_imm(float2 a, float c, float s) {
    return make_float2(fmaf(a.x, c, a.y * (-s)), fmaf(a.y, c, a.x * s));
}
__device__ __forceinline__ float2 cadd(float2 a, float2 b) { return make_float2(a.x + b.x, a.y + b.y); }
__device__ __forceinline__ float2 csub(float2 a, float2 b) { return make_float2(a.x - b.x, a.y - b.y); }
__device__ __forceinline__ float2 muli(float2 a) { return make_float2(-a.y, a.x); }

__device__ __forceinline__ void dft4(float2 x0, float2 x1, float2 x2, float2 x3,
                                     float2& X0, float2& X1, float2& X2, float2& X3) {
    float2 t0 = cadd(x0, x2), t1 = csub(x0, x2);
    float2 t2 = cadd(x1, x3), t3 = csub(x1, x3);
    X0 = cadd(t0, t2);
    X2 = csub(t0, t2);
    float2 it3 = muli(t3);
    X1 = cadd(t1, it3);
    X3 = csub(t1, it3);
}

// inverse 16-point DFT, radix-4x4, natural-order in/out.
__device__ __forceinline__ void ifft16(const float2 x[16], float2 X[16]) {
    const float C  = 0.70710678118654752f;
    const float c1 = 0.92387953251128676f;
    const float s1 = 0.38268343236508977f;
    float2 y[16];
#pragma unroll
    for (int k1 = 0; k1 < 4; ++k1)
        dft4(x[k1], x[k1 + 4], x[k1 + 8], x[k1 + 12],
             y[4 * k1 + 0], y[4 * k1 + 1], y[4 * k1 + 2], y[4 * k1 + 3]);
    y[4 * 1 + 1] = cmul_imm(y[4 * 1 + 1],  c1,  s1);
    y[4 * 1 + 2] = cmul_imm(y[4 * 1 + 2],   C,   C);
    y[4 * 1 + 3] = cmul_imm(y[4 * 1 + 3],  s1,  c1);
    y[4 * 2 + 1] = cmul_imm(y[4 * 2 + 1],   C,   C);
    y[4 * 2 + 2] = muli(y[4 * 2 + 2]);
    y[4 * 2 + 3] = cmul_imm(y[4 * 2 + 3],  -C,   C);
    y[4 * 3 + 1] = cmul_imm(y[4 * 3 + 1],  s1,  c1);
    y[4 * 3 + 2] = cmul_imm(y[4 * 3 + 2],  -C,   C);
    y[4 * 3 + 3] = cmul_imm(y[4 * 3 + 3], -c1, -s1);
#pragma unroll
    for (int n2 = 0; n2 < 4; ++n2) {
        float2 z0, z1, z2, z3;
        dft4(y[4 * 0 + n2], y[4 * 1 + n2], y[4 * 2 + n2], y[4 * 3 + n2], z0, z1, z2, z3);
        X[n2] = z0; X[4 + n2] = z1; X[8 + n2] = z2; X[12 + n2] = z3;
    }
}

// 256-point inverse DFT core: stage-1 input x[k1] already in registers.
__device__ __forceinline__ void fft256_core(const float2 x[16], float2 (*sh)[SH_R],
                                            int line, int k0) {
    float2 X[16];
    ifft16(x, X);
    float sb, cb;
    __sincosf((float)k0 * (TWO_PI / 256.f), &sb, &cb);
    float2 base = make_float2(cb, sb);
    float2 tw = make_float2(1.f, 0.f);
#pragma unroll
    for (int n0 = 0; n0 < 16; ++n0) {
        sh[line][k0 * 17 + n0] = cmul(X[n0], tw);
        tw = cmul(tw, base);
    }
    __syncthreads();
    const int n0 = k0;
    float2 y[16];
#pragma unroll
    for (int kk = 0; kk < 16; ++kk) y[kk] = sh[line][kk * 17 + n0];
    __syncthreads();
    float2 Y[16];
    ifft16(y, Y);
#pragma unroll
    for (int n1 = 0; n1 < 16; ++n1) sh[line][n1 * 16 + n0] = Y[n1];
    __syncthreads();
}

// ----------------------------------------------------------------------------
// Pass 1: inverse DFT along contiguous axis v -> channel-last fp16 g_A[u][v][c].
// MODE 0: Fx [c][y=u][z=v]; MODE 1: Fy [f][x=u][d][z=v]; MODE 2: Fz [f][x=u][y=v][d]
// ----------------------------------------------------------------------------
template <int MODE>
__global__ __launch_bounds__(256) void k_fft_pass1(const float* __restrict__ re,
                                                   const float* __restrict__ im,
                                                   const float* __restrict__ alphap) {
    __shared__ float2 sh[16][SH_R];
    const int t = threadIdx.x;
    const int line = t >> 4, k0 = t & 15;

    const float ap = alphap[0];
    const float bxx = 10.f * ap;
    const float alpha = (bxx > 1.f) ? ap : 0.1f * log1pf(expf(fminf(bxx, 30.f)));

    const int b = blockIdx.x;
    const int u = b & 255;
    const int c0 = (b >> 8) * 16;

    float2 x[16];
    if (MODE == 2) {
        const int f0 = c0 >> 3;
        const int base = f0 * 524288 + u * 2048;
#pragma unroll
        for (int j = 0; j < 16; ++j) {
            int e = t + 256 * j;
            int f_loc = e >> 11, r = e & 2047;
            int d = r & 7, v = r >> 3;
            sh[f_loc * 8 + d][v] = make_float2(re[base + f_loc * 524288 + r] * alpha,
                                               im[base + f_loc * 524288 + r] * alpha);
        }
        __syncthreads();
#pragma unroll
        for (int k1 = 0; k1 < 16; ++k1) x[k1] = sh[line][k1 * 16 + k0];
        __syncthreads();
    } else {
        int c = c0 + line;
        int base;
        if (MODE == 0) base = c * 65536 + u * 256;
        else           base = (c >> 3) * 524288 + u * 2048 + (c & 7) * 256;
#pragma unroll
        for (int k1 = 0; k1 < 16; ++k1) {
            int idx = base + k1 * 16 + k0;
            x[k1] = make_float2(re[idx] * alpha, im[idx] * alpha);
        }
    }
    fft256_core(x, sh, line, k0);

#pragma unroll
    for (int j = 0; j < 16; ++j) {
        int e = t + 256 * j;
        int cl = e & 15, v = e >> 4;
        float2 val = sh[cl][v];
        g_A[(u * 256 + v) * 128 + c0 + cl] = __floats2half2_rn(val.x, val.y);
    }
}

// ----------------------------------------------------------------------------
// Pass 2: inverse DFT along u. Block = 16 channels at one v. Reads L2-hot g_A.
// ----------------------------------------------------------------------------
template <int VOL>
__global__ __launch_bounds__(256) void k_fft_pass2() {
    __shared__ float2 sh[16][SH_R];
    const int t = threadIdx.x;
    const int line = t >> 4, k0 = t & 15;

    const int b = blockIdx.x;
    const int v = b & 255;
    const int c0 = (b >> 8) * 16;

    __half2* __restrict__ V = (VOL == 0) ? g_Vx : (VOL == 1) ? g_Vy : g_Vz;

#pragma unroll
    for (int j = 0; j < 16; ++j) {
        int e = t + 256 * j;
        int cl = e & 15, u = e >> 4;
        sh[cl][u] = __half22float2(g_A[(u * 256 + v) * 128 + c0 + cl]);
    }
    __syncthreads();
    float2 x[16];
#pragma unroll
    for (int k1 = 0; k1 < 16; ++k1) x[k1] = sh[line][k1 * 16 + k0];
    __syncthreads();
    fft256_core(x, sh, line, k0);

#pragma unroll
    for (int j = 0; j < 16; ++j) {
        int e = t + 256 * j;
        int cl = e & 15, u = e >> 4;
        float2 val = sh[cl][u];
        V[(u * 256 + v) * 128 + c0 + cl] = __floats2half2_rn(val.x, val.y);
    }
}

// ----------------------------------------------------------------------------
// Direct sampler (R7 winner): one warp per point, lane = 4 channels.
// 12 tap loads issued up front; twiddle via 1 sincos + recurrence per plane.
// ----------------------------------------------------------------------------
__device__ __forceinline__ int corner_base(float gu, float gv, int& u1d, int& v1d,
                                           float& wu, float& wv) {
    float iu = (gu + 1.f) * 127.5f;
    float iv = (gv + 1.f) * 127.5f;
    float u0f = floorf(iu), v0f = floorf(iv);
    wu = iu - u0f; wv = iv - v0f;
    int u0 = (int)u0f; u0 = max(0, min(u0, 255)); int u1 = min(u0 + 1, 255);
    int v0 = (int)v0f; v0 = max(0, min(v0, 255)); int v1 = min(v0 + 1, 255);
    u1d = (u1 - u0) * 256 * 128;
    v1d = (v1 - v0) * 128;
    return (u0 * 256 + v0) * 128;
}

__device__ __forceinline__ float plane_reduce(const uint4 q[4],
                                              float wu, float wv, float bang, int d0) {
    float w00 = (1.f - wu) * (1.f - wv), w01 = (1.f - wu) * wv;
    float w10 = wu * (1.f - wv),         w11 = wu * wv;
    float sn1, cn1;
    __sincosf(bang, &sn1, &cn1);
    float2 w1 = make_float2(cn1, sn1);
    float2 w2 = cmul(w1, w1);
    float2 w4 = cmul(w2, w2);
    float2 cur = (d0 == 0) ? make_float2(1.f, 0.f) : w4;
    float res = 0.f;
    const unsigned* q00 = (const unsigned*)&q[0];
    const unsigned* q01 = (const unsigned*)&q[1];
    const unsigned* q10 = (const unsigned*)&q[2];
    const unsigned* q11 = (const unsigned*)&q[3];
#pragma unroll
    for (int j = 0; j < 4; ++j) {
        float2 a = __half22float2(*(const __half2*)&q00[j]);
        float2 b = __half22float2(*(const __half2*)&q01[j]);
        float2 c = __half22float2(*(const __half2*)&q10[j]);
        float2 d = __half22float2(*(const __half2*)&q11[j]);
        float sr = w00 * a.x + w01 * b.x + w10 * c.x + w11 * d.x;
        float si = w00 * a.y + w01 * b.y + w10 * c.y + w11 * d.y;
        float sc = (d0 + j > 0) ? 2.f : 1.f;
        res += sc * (sr * cur.x - si * cur.y);
        cur = cmul(cur, w1);
    }
    return res;
}

__global__ __launch_bounds__(256) void k_sample(const float* __restrict__ pts,
                                                float* __restrict__ out) {
    int gw = (blockIdx.x * 256 + threadIdx.x) >> 5;
    int lane = threadIdx.x & 31;
    if (gw >= 131072) return;
    float xs = pts[gw * 3 + 0];
    float ys = pts[gw * 3 + 1];
    float zs = pts[gw * 3 + 2];
    int cbase = lane * 4;
    int d0 = cbase & 7;

    float wuX, wvX, wuY, wvY, wuZ, wvZ;
    int u1X, v1X, u1Y, v1Y, u1Z, v1Z;
    int bX = corner_base(ys, zs, u1X, v1X, wuX, wvX) + cbase;
    int bY = corner_base(xs, zs, u1Y, v1Y, wuY, wvY) + cbase;
    int bZ = corner_base(xs, ys, u1Z, v1Z, wuZ, wvZ) + cbase;

    uint4 qX[4], qY[4], qZ[4];
    qX[0] = *(const uint4*)(g_Vx + bX);
    qX[1] = *(const uint4*)(g_Vx + bX + v1X);
    qX[2] = *(const uint4*)(g_Vx + bX + u1X);
    qX[3] = *(const uint4*)(g_Vx + bX + u1X + v1X);
    qY[0] = *(const uint4*)(g_Vy + bY);
    qY[1] = *(const uint4*)(g_Vy + bY + v1Y);
    qY[2] = *(const uint4*)(g_Vy + bY + u1Y);
    qY[3] = *(const uint4*)(g_Vy + bY + u1Y + v1Y);
    qZ[0] = *(const uint4*)(g_Vz + bZ);
    qZ[1] = *(const uint4*)(g_Vz + bZ + v1Z);
    qZ[2] = *(const uint4*)(g_Vz + bZ + u1Z);
    qZ[3] = *(const uint4*)(g_Vz + bZ + u1Z + v1Z);

    const float K = TWO_PI * 0.5f * (255.f / 256.f);
    float acc = plane_reduce(qX, wuX, wvX, (xs + 1.f) * K, d0)
              + plane_reduce(qY, wuY, wvY, (ys + 1.f) * K, d0)
              + plane_reduce(qZ, wuZ, wvZ, (zs + 1.f) * K, d0);

    acc += __shfl_xor_sync(0xffffffffu, acc, 1);
    float vv = __shfl_sync(0xffffffffu, acc, (lane & 15) * 2);
    if (lane < 16) out[gw * 16 + lane] = vv;
}

extern "C" void kernel_launch(void* const* d_in, const int* in_sizes, int n_in,
                              void* d_out, int out_size) {
    const float* pts    = (const float*)d_in[0];
    const float* Fx_re  = (const float*)d_in[1];
    const float* Fx_im  = (const float*)d_in[2];
    const float* Fy_re  = (const float*)d_in[3];
    const float* Fy_im  = (const float*)d_in[4];
    const float* Fz_re  = (const float*)d_in[5];
    const float* Fz_im  = (const float*)d_in[6];
    const float* alphap = (const float*)d_in[7];
    float* out = (float*)d_out;

    // per-volume pairing keeps g_A (33.5MB) L2-resident between p1 and p2
    k_fft_pass1<0><<<2048, 256>>>(Fx_re, Fx_im, alphap);
    k_fft_pass2<0><<<2048, 256>>>();
    k_fft_pass1<1><<<2048, 256>>>(Fy_re, Fy_im, alphap);
    k_fft_pass2<1><<<2048, 256>>>();
    k_fft_pass1<2><<<2048, 256>>>(Fz_re, Fz_im, alphap);
    k_fft_pass2<2><<<2048, 256>>>();
    k_sample<<<131072 * 32 / 256, 256>>>(pts, out);
}

// round 15
// speedup vs baseline: 1.4823x; 1.4823x over previous
#include <cuda_runtime.h>
#include <cuda_fp16.h>
#include <math.h>

#define TWO_PI 6.283185307179586f

// ---- static device scratch (allocation-free) ----
__device__ __align__(16) __half2 g_A0[256 * 256 * 128];  // fp16 intermediates
__device__ __align__(16) __half2 g_A1[256 * 256 * 128];
__device__ __align__(16) __half2 g_A2[256 * 256 * 128];
__device__ __align__(16) __half2 g_Vx[256 * 256 * 128];  // channel-last volumes
__device__ __align__(16) __half2 g_Vy[256 * 256 * 128];
__device__ __align__(16) __half2 g_Vz[256 * 256 * 128];

#define SH_R 273   // smem row stride (float2 units)

// ---------------------------------------------------------------------------
// complex helpers
// ---------------------------------------------------------------------------
__device__ __forceinline__ float2 cmul(float2 a, float2 b) {
    return make_float2(fmaf(a.x, b.x, -a.y * b.y), fmaf(a.x, b.y, a.y * b.x));
}
__device__ __forceinline__ float2 cmul_imm(float2 a, float c, float s) {
    return make_float2(fmaf(a.x, c, a.y * (-s)), fmaf(a.y, c, a.x * s));
}
__device__ __forceinline__ float2 cadd(float2 a, float2 b) { return make_float2(a.x + b.x, a.y + b.y); }
__device__ __forceinline__ float2 csub(float2 a, float2 b) { return make_float2(a.x - b.x, a.y - b.y); }
__device__ __forceinline__ float2 muli(float2 a) { return make_float2(-a.y, a.x); }

__device__ __forceinline__ void dft4(float2 x0, float2 x1, float2 x2, float2 x3,
                                     float2& X0, float2& X1, float2& X2, float2& X3) {
    float2 t0 = cadd(x0, x2), t1 = csub(x0, x2);
    float2 t2 = cadd(x1, x3), t3 = csub(x1, x3);
    X0 = cadd(t0, t2);
    X2 = csub(t0, t2);
    float2 it3 = muli(t3);
    X1 = cadd(t1, it3);
    X3 = csub(t1, it3);
}

// inverse 16-point DFT, radix-4x4, natural-order in/out.
__device__ __forceinline__ void ifft16(const float2 x[16], float2 X[16]) {
    const float C  = 0.70710678118654752f;
    const float c1 = 0.92387953251128676f;
    const float s1 = 0.38268343236508977f;
    float2 y[16];
#pragma unroll
    for (int k1 = 0; k1 < 4; ++k1)
        dft4(x[k1], x[k1 + 4], x[k1 + 8], x[k1 + 12],
             y[4 * k1 + 0], y[4 * k1 + 1], y[4 * k1 + 2], y[4 * k1 + 3]);
    y[4 * 1 + 1] = cmul_imm(y[4 * 1 + 1],  c1,  s1);
    y[4 * 1 + 2] = cmul_imm(y[4 * 1 + 2],   C,   C);
    y[4 * 1 + 3] = cmul_imm(y[4 * 1 + 3],  s1,  c1);
    y[4 * 2 + 1] = cmul_imm(y[4 * 2 + 1],   C,   C);
    y[4 * 2 + 2] = muli(y[4 * 2 + 2]);
    y[4 * 2 + 3] = cmul_imm(y[4 * 2 + 3],  -C,   C);
    y[4 * 3 + 1] = cmul_imm(y[4 * 3 + 1],  s1,  c1);
    y[4 * 3 + 2] = cmul_imm(y[4 * 3 + 2],  -C,   C);
    y[4 * 3 + 3] = cmul_imm(y[4 * 3 + 3], -c1, -s1);
#pragma unroll
    for (int n2 = 0; n2 < 4; ++n2) {
        float2 z0, z1, z2, z3;
        dft4(y[4 * 0 + n2], y[4 * 1 + n2], y[4 * 2 + n2], y[4 * 3 + n2], z0, z1, z2, z3);
        X[n2] = z0; X[4 + n2] = z1; X[8 + n2] = z2; X[12 + n2] = z3;
    }
}

// 256-point inverse DFT core: stage-1 input x[k1] already in registers.
__device__ __forceinline__ void fft256_core(const float2 x[16], float2 (*sh)[SH_R],
                                            int line, int k0) {
    float2 X[16];
    ifft16(x, X);
    float sb, cb;
    __sincosf((float)k0 * (TWO_PI / 256.f), &sb, &cb);
    float2 base = make_float2(cb, sb);
    float2 tw = make_float2(1.f, 0.f);
#pragma unroll
    for (int n0 = 0; n0 < 16; ++n0) {
        sh[line][k0 * 17 + n0] = cmul(X[n0], tw);
        tw = cmul(tw, base);
    }
    __syncthreads();
    const int n0 = k0;
    float2 y[16];
#pragma unroll
    for (int kk = 0; kk < 16; ++kk) y[kk] = sh[line][kk * 17 + n0];
    __syncthreads();
    float2 Y[16];
    ifft16(y, Y);
#pragma unroll
    for (int n1 = 0; n1 < 16; ++n1) sh[line][n1 * 16 + n0] = Y[n1];
    __syncthreads();
}

// ----------------------------------------------------------------------------
// Pass 1 (all 3 volumes, merged): inverse DFT along contiguous axis v.
// ----------------------------------------------------------------------------
__global__ __launch_bounds__(256) void k_fft_pass1_all(
        const float* __restrict__ x_re, const float* __restrict__ x_im,
        const float* __restrict__ y_re, const float* __restrict__ y_im,
        const float* __restrict__ z_re, const float* __restrict__ z_im,
        const float* __restrict__ alphap) {
    __shared__ float2 sh[16][SH_R];
    const int t = threadIdx.x;
    const int line = t >> 4, k0 = t & 15;

    const float ap = alphap[0];
    const float bxx = 10.f * ap;
    const float alpha = (bxx > 1.f) ? ap : 0.1f * log1pf(expf(fminf(bxx, 30.f)));

    const int bb = blockIdx.x;
    const int mode = bb >> 11;
    const int b = bb & 2047;
    const int u = b & 255;
    const int c0 = (b >> 8) * 16;

    float2 x[16];
    if (mode == 2) {
        const int f0 = c0 >> 3;
        const int base = f0 * 524288 + u * 2048;
#pragma unroll
        for (int j = 0; j < 16; ++j) {
            int e = t + 256 * j;
            int f_loc = e >> 11, r = e & 2047;
            int d = r & 7, v = r >> 3;
            sh[f_loc * 8 + d][v] = make_float2(z_re[base + f_loc * 524288 + r] * alpha,
                                               z_im[base + f_loc * 524288 + r] * alpha);
        }
        __syncthreads();
#pragma unroll
        for (int k1 = 0; k1 < 16; ++k1) x[k1] = sh[line][k1 * 16 + k0];
        __syncthreads();
    } else {
        const float* __restrict__ re = (mode == 0) ? x_re : y_re;
        const float* __restrict__ im = (mode == 0) ? x_im : y_im;
        int c = c0 + line;
        int base;
        if (mode == 0) base = c * 65536 + u * 256;
        else           base = (c >> 3) * 524288 + u * 2048 + (c & 7) * 256;
#pragma unroll
        for (int k1 = 0; k1 < 16; ++k1) {
            int idx = base + k1 * 16 + k0;
            x[k1] = make_float2(re[idx] * alpha, im[idx] * alpha);
        }
    }
    fft256_core(x, sh, line, k0);

    __half2* __restrict__ A = (mode == 0) ? g_A0 : (mode == 1) ? g_A1 : g_A2;
#pragma unroll
    for (int j = 0; j < 16; ++j) {
        int e = t + 256 * j;
        int cl = e & 15, v = e >> 4;
        float2 val = sh[cl][v];
        A[(u * 256 + v) * 128 + c0 + cl] = __floats2half2_rn(val.x, val.y);
    }
}

// ----------------------------------------------------------------------------
// Pass 2 (all 3 volumes, merged): inverse DFT along u. Mode order REVERSED
// (A2 first — it was written last by pass1, so it's the L2-hot one).
// ----------------------------------------------------------------------------
__global__ __launch_bounds__(256) void k_fft_pass2_all() {
    __shared__ float2 sh[16][SH_R];
    const int t = threadIdx.x;
    const int line = t >> 4, k0 = t & 15;

    const int bb = blockIdx.x;
    const int mode = 2 - (bb >> 11);
    const int b = bb & 2047;
    const int v = b & 255;
    const int c0 = (b >> 8) * 16;

    const __half2* __restrict__ A = (mode == 0) ? g_A0 : (mode == 1) ? g_A1 : g_A2;
    __half2* __restrict__ V = (mode == 0) ? g_Vx : (mode == 1) ? g_Vy : g_Vz;

#pragma unroll
    for (int j = 0; j < 16; ++j) {
        int e = t + 256 * j;
        int cl = e & 15, u = e >> 4;
        sh[cl][u] = __half22float2(A[(u * 256 + v) * 128 + c0 + cl]);
    }
    __syncthreads();
    float2 x[16];
#pragma unroll
    for (int k1 = 0; k1 < 16; ++k1) x[k1] = sh[line][k1 * 16 + k0];
    __syncthreads();
    fft256_core(x, sh, line, k0);

#pragma unroll
    for (int j = 0; j < 16; ++j) {
        int e = t + 256 * j;
        int cl = e & 15, u = e >> 4;
        float2 val = sh[cl][u];
        V[(u * 256 + v) * 128 + c0 + cl] = __floats2half2_rn(val.x, val.y);
    }
}

// ----------------------------------------------------------------------------
// Per-plane sampler: one warp per point, lane = 4 channels, ONE volume per
// kernel (100MB working set fits L2). PLANE 2 runs first (g_Vz L2-hot from
// pass2) and writes out; planes 1, 0 accumulate (single owner per element,
// sequential kernels -> no atomics needed).
// ----------------------------------------------------------------------------
__device__ __forceinline__ int corner_base(float gu, float gv, int& u1d, int& v1d,
                                           float& wu, float& wv) {
    float iu = (gu + 1.f) * 127.5f;
    float iv = (gv + 1.f) * 127.5f;
    float u0f = floorf(iu), v0f = floorf(iv);
    wu = iu - u0f; wv = iv - v0f;
    int u0 = (int)u0f; u0 = max(0, min(u0, 255)); int u1 = min(u0 + 1, 255);
    int v0 = (int)v0f; v0 = max(0, min(v0, 255)); int v1 = min(v0 + 1, 255);
    u1d = (u1 - u0) * 256 * 128;
    v1d = (v1 - v0) * 128;
    return (u0 * 256 + v0) * 128;
}

template <int PLANE, bool FIRST>
__global__ __launch_bounds__(256) void k_sample_plane(const float* __restrict__ pts,
                                                      float* __restrict__ out) {
    int gw = (blockIdx.x * 256 + threadIdx.x) >> 5;
    int lane = threadIdx.x & 31;
    float xs = pts[gw * 3 + 0];
    float ys = pts[gw * 3 + 1];
    float zs = pts[gw * 3 + 2];
    int cbase = lane * 4;
    int d0 = cbase & 7;

    float gu, gv, tx;
    const __half2* __restrict__ V;
    if (PLANE == 0)      { V = g_Vx; gu = ys; gv = zs; tx = xs; }
    else if (PLANE == 1) { V = g_Vy; gu = xs; gv = zs; tx = ys; }
    else                 { V = g_Vz; gu = xs; gv = ys; tx = zs; }

    float wu, wv;
    int u1d, v1d;
    int base = corner_base(gu, gv, u1d, v1d, wu, wv) + cbase;

    uint4 q00 = *(const uint4*)(V + base);
    uint4 q01 = *(const uint4*)(V + base + v1d);
    uint4 q10 = *(const uint4*)(V + base + u1d);
    uint4 q11 = *(const uint4*)(V + base + u1d + v1d);

    float w00 = (1.f - wu) * (1.f - wv), w01 = (1.f - wu) * wv;
    float w10 = wu * (1.f - wv),         w11 = wu * wv;

    const float K = TWO_PI * 0.5f * (255.f / 256.f);
    float bang = (tx + 1.f) * K;
    float sn1, cn1;
    __sincosf(bang, &sn1, &cn1);
    float2 w1 = make_float2(cn1, sn1);
    float2 w2 = cmul(w1, w1);
    float2 w4 = cmul(w2, w2);
    float2 cur = (d0 == 0) ? make_float2(1.f, 0.f) : w4;

    const unsigned* a00 = (const unsigned*)&q00;
    const unsigned* a01 = (const unsigned*)&q01;
    const unsigned* a10 = (const unsigned*)&q10;
    const unsigned* a11 = (const unsigned*)&q11;

    float acc = 0.f;
#pragma unroll
    for (int j = 0; j < 4; ++j) {
        float2 a = __half22float2(*(const __half2*)&a00[j]);
        float2 b = __half22float2(*(const __half2*)&a01[j]);
        float2 c = __half22float2(*(const __half2*)&a10[j]);
        float2 d = __half22float2(*(const __half2*)&a11[j]);
        float sr = w00 * a.x + w01 * b.x + w10 * c.x + w11 * d.x;
        float si = w00 * a.y + w01 * b.y + w10 * c.y + w11 * d.y;
        float sc = (d0 + j > 0) ? 2.f : 1.f;
        acc += sc * (sr * cur.x - si * cur.y);
        cur = cmul(cur, w1);
    }

    acc += __shfl_xor_sync(0xffffffffu, acc, 1);
    float vv = __shfl_sync(0xffffffffu, acc, (lane & 15) * 2);
    if (lane < 16) {
        if (FIRST) out[gw * 16 + lane] = vv;
        else       out[gw * 16 + lane] += vv;
    }
}

extern "C" void kernel_launch(void* const* d_in, const int* in_sizes, int n_in,
                              void* d_out, int out_size) {
    const float* pts    = (const float*)d_in[0];
    const float* Fx_re  = (const float*)d_in[1];
    const float* Fx_im  = (const float*)d_in[2];
    const float* Fy_re  = (const float*)d_in[3];
    const float* Fy_im  = (const float*)d_in[4];
    const float* Fz_re  = (const float*)d_in[5];
    const float* Fz_im  = (const float*)d_in[6];
    const float* alphap = (const float*)d_in[7];
    float* out = (float*)d_out;

    const int SGRID = 131072 * 32 / 256;
    k_fft_pass1_all<<<6144, 256>>>(Fx_re, Fx_im, Fy_re, Fy_im, Fz_re, Fz_im, alphap);
    k_fft_pass2_all<<<6144, 256>>>();
    k_sample_plane<2, true ><<<SGRID, 256>>>(pts, out);   // Vz is L2-hot
    k_sample_plane<1, false><<<SGRID, 256>>>(pts, out);
    k_sample_plane<0, false><<<SGRID, 256>>>(pts, out);
}

// round 16
// speedup vs baseline: 1.5793x; 1.0654x over previous
#include <cuda_runtime.h>
#include <cuda_fp16.h>
#include <math.h>

#define TWO_PI 6.283185307179586f

// ---- static device scratch (allocation-free) ----
__device__ __align__(16) __half2 g_A0[256 * 256 * 128];  // fp16 intermediates
__device__ __align__(16) __half2 g_A1[256 * 256 * 128];
__device__ __align__(16) __half2 g_A2[256 * 256 * 128];
__device__ __align__(16) __half2 g_Vx[256 * 256 * 128];  // channel-last volumes
__device__ __align__(16) __half2 g_Vy[256 * 256 * 128];
__device__ __align__(16) __half2 g_Vz[256 * 256 * 128];

#define SH_R 273   // smem row stride (float2 units)

// ---------------------------------------------------------------------------
// complex helpers
// ---------------------------------------------------------------------------
__device__ __forceinline__ float2 cmul(float2 a, float2 b) {
    return make_float2(fmaf(a.x, b.x, -a.y * b.y), fmaf(a.x, b.y, a.y * b.x));
}
__device__ __forceinline__ float2 cmul_imm(float2 a, float c, float s) {
    return make_float2(fmaf(a.x, c, a.y * (-s)), fmaf(a.y, c, a.x * s));
}
__device__ __forceinline__ float2 cadd(float2 a, float2 b) { return make_float2(a.x + b.x, a.y + b.y); }
__device__ __forceinline__ float2 csub(float2 a, float2 b) { return make_float2(a.x - b.x, a.y - b.y); }
__device__ __forceinline__ float2 muli(float2 a) { return make_float2(-a.y, a.x); }

__device__ __forceinline__ void dft4(float2 x0, float2 x1, float2 x2, float2 x3,
                                     float2& X0, float2& X1, float2& X2, float2& X3) {
    float2 t0 = cadd(x0, x2), t1 = csub(x0, x2);
    float2 t2 = cadd(x1, x3), t3 = csub(x1, x3);
    X0 = cadd(t0, t2);
    X2 = csub(t0, t2);
    float2 it3 = muli(t3);
    X1 = cadd(t1, it3);
    X3 = csub(t1, it3);
}

// inverse 16-point DFT, radix-4x4, natural-order in/out.
__device__ __forceinline__ void ifft16(const float2 x[16], float2 X[16]) {
    const float C  = 0.70710678118654752f;
    const float c1 = 0.92387953251128676f;
    const float s1 = 0.38268343236508977f;
    float2 y[16];
#pragma unroll
    for (int k1 = 0; k1 < 4; ++k1)
        dft4(x[k1], x[k1 + 4], x[k1 + 8], x[k1 + 12],
             y[4 * k1 + 0], y[4 * k1 + 1], y[4 * k1 + 2], y[4 * k1 + 3]);
    y[4 * 1 + 1] = cmul_imm(y[4 * 1 + 1],  c1,  s1);
    y[4 * 1 + 2] = cmul_imm(y[4 * 1 + 2],   C,   C);
    y[4 * 1 + 3] = cmul_imm(y[4 * 1 + 3],  s1,  c1);
    y[4 * 2 + 1] = cmul_imm(y[4 * 2 + 1],   C,   C);
    y[4 * 2 + 2] = muli(y[4 * 2 + 2]);
    y[4 * 2 + 3] = cmul_imm(y[4 * 2 + 3],  -C,   C);
    y[4 * 3 + 1] = cmul_imm(y[4 * 3 + 1],  s1,  c1);
    y[4 * 3 + 2] = cmul_imm(y[4 * 3 + 2],  -C,   C);
    y[4 * 3 + 3] = cmul_imm(y[4 * 3 + 3], -c1, -s1);
#pragma unroll
    for (int n2 = 0; n2 < 4; ++n2) {
        float2 z0, z1, z2, z3;
        dft4(y[4 * 0 + n2], y[4 * 1 + n2], y[4 * 2 + n2], y[4 * 3 + n2], z0, z1, z2, z3);
        X[n2] = z0; X[4 + n2] = z1; X[8 + n2] = z2; X[12 + n2] = z3;
    }
}

// 256-point inverse DFT core: stage-1 input x[k1] already in registers.
__device__ __forceinline__ void fft256_core(const float2 x[16], float2 (*sh)[SH_R],
                                            int line, int k0) {
    float2 X[16];
    ifft16(x, X);
    float sb, cb;
    __sincosf((float)k0 * (TWO_PI / 256.f), &sb, &cb);
    float2 base = make_float2(cb, sb);
    float2 tw = make_float2(1.f, 0.f);
#pragma unroll
    for (int n0 = 0; n0 < 16; ++n0) {
        sh[line][k0 * 17 + n0] = cmul(X[n0], tw);
        tw = cmul(tw, base);
    }
    __syncthreads();
    const int n0 = k0;
    float2 y[16];
#pragma unroll
    for (int kk = 0; kk < 16; ++kk) y[kk] = sh[line][kk * 17 + n0];
    __syncthreads();
    float2 Y[16];
    ifft16(y, Y);
#pragma unroll
    for (int n1 = 0; n1 < 16; ++n1) sh[line][n1 * 16 + n0] = Y[n1];
    __syncthreads();
}

// ----------------------------------------------------------------------------
// Pass 1 (all 3 volumes, merged): inverse DFT along contiguous axis v.
// ----------------------------------------------------------------------------
__global__ __launch_bounds__(256) void k_fft_pass1_all(
        const float* __restrict__ x_re, const float* __restrict__ x_im,
        const float* __restrict__ y_re, const float* __restrict__ y_im,
        const float* __restrict__ z_re, const float* __restrict__ z_im,
        const float* __restrict__ alphap) {
    __shared__ float2 sh[16][SH_R];
    const int t = threadIdx.x;
    const int line = t >> 4, k0 = t & 15;

    const float ap = alphap[0];
    const float bxx = 10.f * ap;
    const float alpha = (bxx > 1.f) ? ap : 0.1f * log1pf(expf(fminf(bxx, 30.f)));

    const int bb = blockIdx.x;
    const int mode = bb >> 11;
    const int b = bb & 2047;
    const int u = b & 255;
    const int c0 = (b >> 8) * 16;

    float2 x[16];
    if (mode == 2) {
        const int f0 = c0 >> 3;
        const int base = f0 * 524288 + u * 2048;
#pragma unroll
        for (int j = 0; j < 16; ++j) {
            int e = t + 256 * j;
            int f_loc = e >> 11, r = e & 2047;
            int d = r & 7, v = r >> 3;
            sh[f_loc * 8 + d][v] = make_float2(z_re[base + f_loc * 524288 + r] * alpha,
                                               z_im[base + f_loc * 524288 + r] * alpha);
        }
        __syncthreads();
#pragma unroll
        for (int k1 = 0; k1 < 16; ++k1) x[k1] = sh[line][k1 * 16 + k0];
        __syncthreads();
    } else {
        const float* __restrict__ re = (mode == 0) ? x_re : y_re;
        const float* __restrict__ im = (mode == 0) ? x_im : y_im;
        int c = c0 + line;
        int base;
        if (mode == 0) base = c * 65536 + u * 256;
        else           base = (c >> 3) * 524288 + u * 2048 + (c & 7) * 256;
#pragma unroll
        for (int k1 = 0; k1 < 16; ++k1) {
            int idx = base + k1 * 16 + k0;
            x[k1] = make_float2(re[idx] * alpha, im[idx] * alpha);
        }
    }
    fft256_core(x, sh, line, k0);

    __half2* __restrict__ A = (mode == 0) ? g_A0 : (mode == 1) ? g_A1 : g_A2;
#pragma unroll
    for (int j = 0; j < 16; ++j) {
        int e = t + 256 * j;
        int cl = e & 15, v = e >> 4;
        float2 val = sh[cl][v];
        A[(u * 256 + v) * 128 + c0 + cl] = __floats2half2_rn(val.x, val.y);
    }
}

// ----------------------------------------------------------------------------
// Pass 2 (all 3 volumes, merged): inverse DFT along u. Mode order reversed
// (A2 first — written last by pass1 -> L2-hot).
// ----------------------------------------------------------------------------
__global__ __launch_bounds__(256) void k_fft_pass2_all() {
    __shared__ float2 sh[16][SH_R];
    const int t = threadIdx.x;
    const int line = t >> 4, k0 = t & 15;

    const int bb = blockIdx.x;
    const int mode = 2 - (bb >> 11);
    const int b = bb & 2047;
    const int v = b & 255;
    const int c0 = (b >> 8) * 16;

    const __half2* __restrict__ A = (mode == 0) ? g_A0 : (mode == 1) ? g_A1 : g_A2;
    __half2* __restrict__ V = (mode == 0) ? g_Vx : (mode == 1) ? g_Vy : g_Vz;

#pragma unroll
    for (int j = 0; j < 16; ++j) {
        int e = t + 256 * j;
        int cl = e & 15, u = e >> 4;
        sh[cl][u] = __half22float2(A[(u * 256 + v) * 128 + c0 + cl]);
    }
    __syncthreads();
    float2 x[16];
#pragma unroll
    for (int k1 = 0; k1 < 16; ++k1) x[k1] = sh[line][k1 * 16 + k0];
    __syncthreads();
    fft256_core(x, sh, line, k0);

#pragma unroll
    for (int j = 0; j < 16; ++j) {
        int e = t + 256 * j;
        int cl = e & 15, u = e >> 4;
        float2 val = sh[cl][u];
        V[(u * 256 + v) * 128 + c0 + cl] = __floats2half2_rn(val.x, val.y);
    }
}

// ----------------------------------------------------------------------------
// Per-plane sampler, half2 bilinear math (issue-bound -> cut instructions).
// One warp per point, lane = 4 channels. Plane 2 first (g_Vz L2-hot), then
// 1 and 0 accumulate into out (single owner per element, no atomics).
// ----------------------------------------------------------------------------
__device__ __forceinline__ int corner_base(float gu, float gv, int& u1d, int& v1d,
                                           float& wu, float& wv) {
    float iu = (gu + 1.f) * 127.5f;
    float iv = (gv + 1.f) * 127.5f;
    float u0f = floorf(iu), v0f = floorf(iv);
    wu = iu - u0f; wv = iv - v0f;
    int u0 = (int)u0f; u0 = max(0, min(u0, 255)); int u1 = min(u0 + 1, 255);
    int v0 = (int)v0f; v0 = max(0, min(v0, 255)); int v1 = min(v0 + 1, 255);
    u1d = (u1 - u0) * 256 * 128;
    v1d = (v1 - v0) * 128;
    return (u0 * 256 + v0) * 128;
}

template <int PLANE, bool FIRST>
__global__ __launch_bounds__(256) void k_sample_plane(const float* __restrict__ pts,
                                                      float* __restrict__ out) {
    int gw = (blockIdx.x * 256 + threadIdx.x) >> 5;
    int lane = threadIdx.x & 31;
    float xs = pts[gw * 3 + 0];
    float ys = pts[gw * 3 + 1];
    float zs = pts[gw * 3 + 2];
    int cbase = lane * 4;
    int d0 = cbase & 7;

    float gu, gv, tx;
    const __half2* __restrict__ V;
    if (PLANE == 0)      { V = g_Vx; gu = ys; gv = zs; tx = xs; }
    else if (PLANE == 1) { V = g_Vy; gu = xs; gv = zs; tx = ys; }
    else                 { V = g_Vz; gu = xs; gv = ys; tx = zs; }

    float wu, wv;
    int u1d, v1d;
    int base = corner_base(gu, gv, u1d, v1d, wu, wv) + cbase;

    uint4 q00 = *(const uint4*)(V + base);
    uint4 q01 = *(const uint4*)(V + base + v1d);
    uint4 q10 = *(const uint4*)(V + base + u1d);
    uint4 q11 = *(const uint4*)(V + base + u1d + v1d);

    // fp16 bilinear weights (packed to both halves)
    __half2 w00h = __float2half2_rn((1.f - wu) * (1.f - wv));
    __half2 w01h = __float2half2_rn((1.f - wu) * wv);
    __half2 w10h = __float2half2_rn(wu * (1.f - wv));
    __half2 w11h = __float2half2_rn(wu * wv);

    const float K = TWO_PI * 0.5f * (255.f / 256.f);
    float bang = (tx + 1.f) * K;
    float sn1, cn1;
    __sincosf(bang, &sn1, &cn1);
    float2 w1 = make_float2(cn1, sn1);
    float2 w2 = cmul(w1, w1);
    float2 w4 = cmul(w2, w2);
    float2 cur = (d0 == 0) ? make_float2(1.f, 0.f) : w4;

    const __half2* a00 = (const __half2*)&q00;
    const __half2* a01 = (const __half2*)&q01;
    const __half2* a10 = (const __half2*)&q10;
    const __half2* a11 = (const __half2*)&q11;

    float acc = 0.f;
#pragma unroll
    for (int j = 0; j < 4; ++j) {
        __half2 s = __hmul2(a00[j], w00h);
        s = __hfma2(a01[j], w01h, s);
        s = __hfma2(a10[j], w10h, s);
        s = __hfma2(a11[j], w11h, s);
        float2 sf = __half22float2(s);
        float sc = (d0 + j > 0) ? 2.f : 1.f;
        acc += sc * (sf.x * cur.x - sf.y * cur.y);
        cur = cmul(cur, w1);
    }

    acc += __shfl_xor_sync(0xffffffffu, acc, 1);
    float vv = __shfl_sync(0xffffffffu, acc, (lane & 15) * 2);
    if (lane < 16) {
        if (FIRST) out[gw * 16 + lane] = vv;
        else       out[gw * 16 + lane] += vv;
    }
}

extern "C" void kernel_launch(void* const* d_in, const int* in_sizes, int n_in,
                              void* d_out, int out_size) {
    const float* pts    = (const float*)d_in[0];
    const float* Fx_re  = (const float*)d_in[1];
    const float* Fx_im  = (const float*)d_in[2];
    const float* Fy_re  = (const float*)d_in[3];
    const float* Fy_im  = (const float*)d_in[4];
    const float* Fz_re  = (const float*)d_in[5];
    const float* Fz_im  = (const float*)d_in[6];
    const float* alphap = (const float*)d_in[7];
    float* out = (float*)d_out;

    const int SGRID = 131072 * 32 / 256;
    k_fft_pass1_all<<<6144, 256>>>(Fx_re, Fx_im, Fy_re, Fy_im, Fz_re, Fz_im, alphap);
    k_fft_pass2_all<<<6144, 256>>>();
    k_sample_plane<2, true ><<<SGRID, 256>>>(pts, out);   // Vz is L2-hot
    k_sample_plane<1, false><<<SGRID, 256>>>(pts, out);
    k_sample_plane<0, false><<<SGRID, 256>>>(pts, out);
}